// round 16
// baseline (speedup 1.0000x reference)
#include <cuda_runtime.h>
#include <cstdint>

#define BB     256
#define TT     32
#define CNN    512
#define HWSQ   196      // 14*14
#define HID    8
#define NG     32       // 4*HID gates
#define VV     37
#define CHUNKS 8                 // pooling CTAs per batch
#define CPB    (CNN/CHUNKS)      // 64 channels per CTA
#define NTHR   256
#define NWARP  (NTHR/32)         // 8
#define CPW    (CPB/NWARP)       // 8 channels per warp
#define UNR    4
#define CAPROW ((TT-1)*VV)       // 1147 caption floats per batch

__device__ float g_x0p[BB * CHUNKS * VV];   // fc_in partial dots
__device__ int   g_cnt[BB];                 // fan-in counters (self-resetting)

__device__ __forceinline__ unsigned long long mk_policy_evict_last() {
    unsigned long long p;
    asm("createpolicy.fractional.L2::evict_last.b64 %0, 1.0;" : "=l"(p));
    return p;
}

__device__ __forceinline__ float4 ldg_el(const float4* p, unsigned long long pol) {
    float4 v;
    asm volatile("ld.global.nc.L2::cache_hint.v4.f32 {%0,%1,%2,%3}, [%4], %5;"
                 : "=f"(v.x), "=f"(v.y), "=f"(v.z), "=f"(v.w)
                 : "l"(p), "l"(pol));
    return v;
}

__device__ __forceinline__ float tanh_fast(float x) {
    float y;
    asm("tanh.approx.f32 %0, %1;" : "=f"(y) : "f"(x));
    return y;
}
__device__ __forceinline__ float sigmoid_fast(float x) {
    return fmaf(0.5f, tanh_fast(0.5f * x), 0.5f);
}

// ---------------------------------------------------------------------------
// Single fan-in kernel. grid = 2048 (8 CTAs/batch, balanced streaming),
// block = 256. Each CTA pools 64 channels + writes fc_in partials. The 8th
// arriver per batch runs the slim all-smem tail, overlapped with the
// remaining batches' streaming.
// ---------------------------------------------------------------------------
__global__ __launch_bounds__(NTHR, 6) void lstm_fanin_kernel(
    const float* __restrict__ feat,     // [B, 512, 14, 14]
    const float* __restrict__ captions, // [B, T, V]
    const float* __restrict__ W_ih,     // [32, 37]
    const float* __restrict__ b_ih,     // [32]
    const float* __restrict__ W_hh,     // [32, 8]
    const float* __restrict__ b_hh,     // [32]
    const float* __restrict__ W_in,     // [37, 512]
    const float* __restrict__ b_in,     // [37]
    const float* __restrict__ W_out,    // [37, 8]
    const float* __restrict__ b_out,    // [37]
    float* __restrict__ out)            // [B, T, V]
{
    __shared__ float spool[CPB];        // 64 channel means (pool phase)
    // tail arrays (used only by the last arriver)
    __shared__ float scap[CAPROW];
    __shared__ float sWih[NG * VV];
    __shared__ float sWhh[NG * 9];      // padded stride 9
    __shared__ float sWout[VV * 9];     // padded stride 9
    __shared__ float sb[NG];
    __shared__ float sbo[VV];
    __shared__ float sbin[VV];
    __shared__ float sx0p[CHUNKS * VV];
    __shared__ float xs[VV];
    __shared__ float xproj[TT * NG];
    __shared__ float hbuf[TT * HID];
    __shared__ float logits[TT * VV];
    __shared__ int   s_last;

    const int b     = blockIdx.x >> 3;
    const int chunk = blockIdx.x & 7;
    const int tid   = threadIdx.x;
    const int warp  = tid >> 5;
    const int lane  = tid & 31;

    // ================= pool my 64 channels (evict_last stream) ==========
    {
        const unsigned long long pol = mk_policy_evict_last();
        const float4* base = reinterpret_cast<const float4*>(feat + (size_t)b * CNN * HWSQ);
        const int c0 = chunk * CPB + warp * CPW;
        #pragma unroll
        for (int cc = 0; cc < CPW; cc += UNR) {
            float4 a[UNR], q[UNR];
            #pragma unroll
            for (int u = 0; u < UNR; ++u) {
                const float4* p = base + (size_t)(c0 + cc + u) * 49;  // 196 floats
                a[u] = ldg_el(p + lane, pol);
                if (lane < 17) q[u] = ldg_el(p + lane + 32, pol);
            }
            float s[UNR];
            #pragma unroll
            for (int u = 0; u < UNR; ++u) {
                s[u] = a[u].x + a[u].y + a[u].z + a[u].w;
                if (lane < 17) s[u] += q[u].x + q[u].y + q[u].z + q[u].w;
            }
            #pragma unroll
            for (int o = 16; o > 0; o >>= 1) {
                #pragma unroll
                for (int u = 0; u < UNR; ++u)
                    s[u] += __shfl_down_sync(0xffffffffu, s[u], o);
            }
            if (lane == 0) {
                #pragma unroll
                for (int u = 0; u < UNR; ++u)
                    spool[warp * CPW + cc + u] = s[u] * (1.0f / 196.0f);
            }
        }
    }
    __syncthreads();

    // ============ fc_in partial dots over my 64 channels ================
    {
        const float p1 = spool[lane];
        const float p2 = spool[lane + 32];
        for (int v = warp; v < VV; v += NWARP) {
            const float* wr = W_in + v * CNN + chunk * CPB;
            float s = p1 * wr[lane] + p2 * wr[lane + 32];
            #pragma unroll
            for (int o = 16; o > 0; o >>= 1)
                s += __shfl_down_sync(0xffffffffu, s, o);
            if (lane == 0)
                g_x0p[(b * CHUNKS + chunk) * VV + v] = s;
        }
    }

    // ================= fan-in: 8th arriver continues ====================
    __threadfence();
    __syncthreads();
    if (tid == 0) {
        int old = atomicAdd(&g_cnt[b], 1);
        s_last = (old == CHUNKS - 1);
        if (s_last) g_cnt[b] = 0;        // reset for next graph replay
    }
    __syncthreads();
    if (!s_last) return;
    __threadfence();                     // acquire other CTAs' g_x0p writes

    // ================= slim tail (all-smem after one staging) ===========
    for (int i = tid; i < CAPROW; i += NTHR)
        scap[i] = captions[(size_t)b * TT * VV + i];
    for (int i = tid; i < NG * VV; i += NTHR) sWih[i] = W_ih[i];
    for (int i = tid; i < NG * HID; i += NTHR) sWhh[(i >> 3) * 9 + (i & 7)] = W_hh[i];
    for (int i = tid; i < VV * HID; i += NTHR) sWout[(i / 8) * 9 + (i & 7)] = W_out[i];
    for (int i = tid; i < CHUNKS * VV; i += NTHR) sx0p[i] = g_x0p[b * CHUNKS * VV + i];
    if (tid < NG) sb[tid]  = b_ih[tid] + b_hh[tid];
    if (tid < VV) sbo[tid] = b_out[tid];
    if (tid < VV) sbin[tid] = b_in[tid];
    __syncthreads();

    // x0 = b_in + 8 chunk partials (fixed order)
    if (tid < VV) {
        float x = sbin[tid];
        #pragma unroll
        for (int c = 0; c < CHUNKS; ++c)
            x += sx0p[c * VV + tid];
        xs[tid] = x;
    }
    __syncthreads();

    // xproj: warp w handles t = w, w+8, w+16, w+24
    for (int t = warp; t < TT; t += NWARP) {
        const float* x = (t == 0) ? xs : &scap[(t - 1) * VV];
        float acc = sb[lane];
        const float* wrow = &sWih[lane * VV];
        #pragma unroll
        for (int k = 0; k < VV; ++k)
            acc = fmaf(x[k], wrow[k], acc);
        xproj[t * NG + lane] = acc;
    }
    __syncthreads();

    // recurrence (warp 0, pipelined xproj prefetch)
    if (warp == 0) {
        float whh0 = sWhh[lane * 9 + 0], whh1 = sWhh[lane * 9 + 1];
        float whh2 = sWhh[lane * 9 + 2], whh3 = sWhh[lane * 9 + 3];
        float whh4 = sWhh[lane * 9 + 4], whh5 = sWhh[lane * 9 + 5];
        float whh6 = sWhh[lane * 9 + 6], whh7 = sWhh[lane * 9 + 7];

        float h0 = 0.f, h1 = 0.f, h2 = 0.f, h3 = 0.f;
        float h4 = 0.f, h5 = 0.f, h6 = 0.f, h7 = 0.f;
        float c = 0.f;
        const int j8 = lane & 7;

        float xp = xproj[lane];              // t = 0 row
        #pragma unroll
        for (int t = 0; t < TT; ++t) {
            float xpn = (t < TT - 1) ? xproj[(t + 1) * NG + lane] : 0.0f;

            float ga = xp;
            float gb = 0.0f;
            ga = fmaf(h0, whh0, ga);  gb = fmaf(h1, whh1, gb);
            ga = fmaf(h2, whh2, ga);  gb = fmaf(h3, whh3, gb);
            ga = fmaf(h4, whh4, ga);  gb = fmaf(h5, whh5, gb);
            ga = fmaf(h6, whh6, ga);  gb = fmaf(h7, whh7, gb);
            float gate = ga + gb;

            float gi = __shfl_sync(0xffffffffu, gate, j8);
            float gf = __shfl_sync(0xffffffffu, gate, j8 + 8);
            float gg = __shfl_sync(0xffffffffu, gate, j8 + 16);
            float go = __shfl_sync(0xffffffffu, gate, j8 + 24);

            float i_ = sigmoid_fast(gi);
            float f_ = sigmoid_fast(gf);
            float g_ = tanh_fast(gg);
            float o_ = sigmoid_fast(go);
            c = fmaf(f_, c, i_ * g_);
            float hn = o_ * tanh_fast(c);

            h0 = __shfl_sync(0xffffffffu, hn, 0);
            h1 = __shfl_sync(0xffffffffu, hn, 1);
            h2 = __shfl_sync(0xffffffffu, hn, 2);
            h3 = __shfl_sync(0xffffffffu, hn, 3);
            h4 = __shfl_sync(0xffffffffu, hn, 4);
            h5 = __shfl_sync(0xffffffffu, hn, 5);
            h6 = __shfl_sync(0xffffffffu, hn, 6);
            h7 = __shfl_sync(0xffffffffu, hn, 7);

            if (lane < HID) hbuf[t * HID + lane] = hn;
            xp = xpn;
        }
    }
    __syncthreads();

    // fc_out: warp w handles t = w, w+8, ... (all smem)
    for (int t = warp; t < TT; t += NWARP) {
        float acc1 = sbo[lane];
        float acc2 = (lane < VV - 32) ? sbo[32 + lane] : 0.0f;
        #pragma unroll
        for (int j = 0; j < HID; ++j) {
            float hv = hbuf[t * HID + j];
            acc1 = fmaf(hv, sWout[lane * 9 + j], acc1);
            if (lane < VV - 32)
                acc2 = fmaf(hv, sWout[(32 + lane) * 9 + j], acc2);
        }
        logits[t * VV + lane] = acc1;
        if (lane < VV - 32) logits[t * VV + 32 + lane] = acc2;
    }
    __syncthreads();

    // parallel softmax over TIME + fused store.
    // 4-lane subgroup per column: v = warp*8 + (lane>>2), 8 t's per lane.
    {
        const int sg = lane >> 2;            // 0..7
        const int sl = lane & 3;             // t = sl + 4k, k = 0..7
        const int v  = warp * 8 + sg;        // 0..63; valid if < VV
        const int vc = (v < VV) ? v : 0;

        float x[8];
        #pragma unroll
        for (int k = 0; k < 8; ++k)
            x[k] = logits[(sl + 4 * k) * VV + vc];

        float m = x[0];
        #pragma unroll
        for (int k = 1; k < 8; ++k) m = fmaxf(m, x[k]);
        #pragma unroll
        for (int o = 2; o > 0; o >>= 1)
            m = fmaxf(m, __shfl_xor_sync(0xffffffffu, m, o, 4));

        float e[8];
        float s = 0.0f;
        #pragma unroll
        for (int k = 0; k < 8; ++k) { e[k] = __expf(x[k] - m); s += e[k]; }
        #pragma unroll
        for (int o = 2; o > 0; o >>= 1)
            s += __shfl_xor_sync(0xffffffffu, s, o, 4);
        float r = 1.0f / s;

        if (v < VV) {
            float* ob = out + (size_t)b * TT * VV + v;
            #pragma unroll
            for (int k = 0; k < 8; ++k)
                ob[(sl + 4 * k) * VV] = e[k] * r;
        }
    }
}

// ---------------------------------------------------------------------------
extern "C" void kernel_launch(void* const* d_in, const int* in_sizes, int n_in,
                              void* d_out, int out_size)
{
    const float* features = (const float*)d_in[0];
    const float* captions = (const float*)d_in[1];
    const float* W_ih     = (const float*)d_in[2];
    const float* b_ih     = (const float*)d_in[3];
    const float* W_hh     = (const float*)d_in[4];
    const float* b_hh     = (const float*)d_in[5];
    const float* W_in     = (const float*)d_in[6];
    const float* b_in     = (const float*)d_in[7];
    const float* W_out    = (const float*)d_in[8];
    const float* b_out    = (const float*)d_in[9];
    float* out = (float*)d_out;

    lstm_fanin_kernel<<<BB * CHUNKS, NTHR>>>(features, captions, W_ih, b_ih,
                                             W_hh, b_hh, W_in, b_in,
                                             W_out, b_out, out);
    (void)in_sizes; (void)n_in; (void)out_size;
}

// round 17
// speedup vs baseline: 1.7802x; 1.7802x over previous
#include <cuda_runtime.h>
#include <cstdint>

#define BB   256
#define TT   32
#define CNN  512
#define HWSQ 196      // 14*14
#define HID  8
#define NG   32       // 4*HID gates
#define VV   37
#define NTHR 512
#define NWARP (NTHR/32)
#define CPW  (CNN/NWARP)   // 32 channels per warp
#define UNR  4             // channels reduced per batch of loads
#define CAPROW ((TT-1)*VV) // 1147 caption floats per batch

__device__ __forceinline__ unsigned long long mk_policy_evict_last() {
    unsigned long long p;
    asm("createpolicy.fractional.L2::evict_last.b64 %0, 1.0;" : "=l"(p));
    return p;
}

__device__ __forceinline__ float4 ldg_el(const float4* p, unsigned long long pol) {
    float4 v;
    asm volatile("ld.global.nc.L2::cache_hint.v4.f32 {%0,%1,%2,%3}, [%4], %5;"
                 : "=f"(v.x), "=f"(v.y), "=f"(v.z), "=f"(v.w)
                 : "l"(p), "l"(pol));
    return v;
}

__device__ __forceinline__ float tanh_fast(float x) {
    float y;
    asm("tanh.approx.f32 %0, %1;" : "=f"(y) : "f"(x));
    return y;
}

// ---------------------------------------------------------------------------
// Fully fused kernel (r14 base = best measured). grid = 256, block = 512.
// r17 deltas: activation-before-gather recurrence (1 MUFU pre-shuffle instead
// of 4 post-shuffle); fc_in batched W_in loads across all 16 warps.
// ---------------------------------------------------------------------------
__global__ __launch_bounds__(NTHR) void lstm_fused_kernel(
    const float* __restrict__ feat,     // [B, 512, 14, 14]
    const float* __restrict__ captions, // [B, T, V]
    const float* __restrict__ W_ih,     // [32, 37]
    const float* __restrict__ b_ih,     // [32]
    const float* __restrict__ W_hh,     // [32, 8]
    const float* __restrict__ b_hh,     // [32]
    const float* __restrict__ W_in,     // [37, 512]
    const float* __restrict__ b_in,     // [37]
    const float* __restrict__ W_out,    // [37, 8]
    const float* __restrict__ b_out,    // [37]
    float* __restrict__ out)            // [B, T, V]
{
    __shared__ float pooled[CNN];
    __shared__ float xs[VV];
    __shared__ float sWih[NG * VV];
    __shared__ float sWout[VV * 9];     // padded stride 9
    __shared__ float sb[NG];
    __shared__ float sbo[VV];
    __shared__ float sbin[VV];
    __shared__ float scap[CAPROW];
    __shared__ float xproj[TT * NG];
    __shared__ float hbuf[TT * HID];
    __shared__ float logits[TT * VV];

    const int b    = blockIdx.x;
    const int tid  = threadIdx.x;
    const int warp = tid >> 5;
    const int lane = tid & 31;

    // ---- stage ALL small globals up front (completes under pooling) ----
    for (int i = tid; i < NG * VV; i += NTHR) sWih[i] = W_ih[i];
    for (int i = tid; i < VV * HID; i += NTHR) sWout[(i / 8) * 9 + (i & 7)] = W_out[i];
    for (int i = tid; i < CAPROW; i += NTHR) scap[i] = captions[(size_t)b * TT * VV + i];
    if (tid < NG) sb[tid]  = b_ih[tid] + b_hh[tid];
    if (tid < VV) sbo[tid] = b_out[tid];
    if (tid < VV) sbin[tid] = b_in[tid];

    // ---- Phase 1: adaptive avg pool (warp owns 32 contiguous channels) ----
    const unsigned long long pol = mk_policy_evict_last();
    const float4* base = reinterpret_cast<const float4*>(feat + (size_t)b * CNN * HWSQ);
    const int c0 = warp * CPW;
    #pragma unroll
    for (int cc = 0; cc < CPW; cc += UNR) {
        float4 a[UNR], q[UNR];
        #pragma unroll
        for (int u = 0; u < UNR; ++u) {
            const float4* p = base + (size_t)(c0 + cc + u) * 49;   // 196 floats
            a[u] = ldg_el(p + lane, pol);
            if (lane < 17) q[u] = ldg_el(p + lane + 32, pol);
        }
        float s[UNR];
        #pragma unroll
        for (int u = 0; u < UNR; ++u) {
            s[u] = a[u].x + a[u].y + a[u].z + a[u].w;
            if (lane < 17) s[u] += q[u].x + q[u].y + q[u].z + q[u].w;
        }
        #pragma unroll
        for (int o = 16; o > 0; o >>= 1) {
            #pragma unroll
            for (int u = 0; u < UNR; ++u)
                s[u] += __shfl_down_sync(0xffffffffu, s[u], o);
        }
        if (lane == 0) {
            #pragma unroll
            for (int u = 0; u < UNR; ++u)
                pooled[c0 + cc + u] = s[u] * (1.0f / 196.0f);
        }
    }
    __syncthreads();

    // ---- Phase 2: fc_in, all 16 warps, batched W_in loads ----
    for (int v = warp; v < VV; v += NWARP) {
        const float* w = W_in + v * CNN;
        float r[16];
        #pragma unroll
        for (int j = 0; j < 16; ++j)
            r[j] = w[lane + 32 * j];
        float s1 = 0.0f, s2 = 0.0f;
        #pragma unroll
        for (int j = 0; j < 16; j += 2) {
            s1 = fmaf(pooled[lane + 32 * j],       r[j],     s1);
            s2 = fmaf(pooled[lane + 32 * (j + 1)], r[j + 1], s2);
        }
        float s = s1 + s2;
        #pragma unroll
        for (int o = 16; o > 0; o >>= 1)
            s += __shfl_down_sync(0xffffffffu, s, o);
        if (lane == 0) xs[v] = s + sbin[v];
    }
    __syncthreads();

    // ---- Phase 3: xproj (warp w handles t = w, w+16) — pure smem ----
    for (int t = warp; t < TT; t += NWARP) {
        const float* x = (t == 0) ? xs : &scap[(t - 1) * VV];
        float acc = sb[lane];
        const float* wrow = &sWih[lane * VV];
        #pragma unroll
        for (int k = 0; k < VV; ++k)
            acc = fmaf(x[k], wrow[k], acc);
        xproj[t * NG + lane] = acc;
    }
    __syncthreads();

    // ---- Phase 4: recurrence (warp 0, activation-before-gather) ----
    if (warp == 0) {
        const float4* w4 = reinterpret_cast<const float4*>(W_hh);
        float4 wa = w4[lane * 2];
        float4 wb = w4[lane * 2 + 1];
        float whh0 = wa.x, whh1 = wa.y, whh2 = wa.z, whh3 = wa.w;
        float whh4 = wb.x, whh5 = wb.y, whh6 = wb.z, whh7 = wb.w;

        float h0 = 0.f, h1 = 0.f, h2 = 0.f, h3 = 0.f;
        float h4 = 0.f, h5 = 0.f, h6 = 0.f, h7 = 0.f;
        float c = 0.f;
        const int j8 = lane & 7;
        // lanes 16..23 hold the 'g' gate (tanh); others sigmoid
        const bool isG = (lane >= 16) && (lane < 24);
        const float preScale = isG ? 1.0f : 0.5f;

        float xp = xproj[lane];              // t = 0 row
        #pragma unroll
        for (int t = 0; t < TT; ++t) {
            float xpn = (t < TT - 1) ? xproj[(t + 1) * NG + lane] : 0.0f;

            float ga = xp;
            float gb = 0.0f;
            ga = fmaf(h0, whh0, ga);  gb = fmaf(h1, whh1, gb);
            ga = fmaf(h2, whh2, ga);  gb = fmaf(h3, whh3, gb);
            ga = fmaf(h4, whh4, ga);  gb = fmaf(h5, whh5, gb);
            ga = fmaf(h6, whh6, ga);  gb = fmaf(h7, whh7, gb);
            float gate = ga + gb;

            // activation on own lane BEFORE gather (1 MUFU on the path)
            float tz  = tanh_fast(gate * preScale);
            float act = isG ? tz : fmaf(0.5f, tz, 0.5f);

            float i_ = __shfl_sync(0xffffffffu, act, j8);
            float f_ = __shfl_sync(0xffffffffu, act, j8 + 8);
            float g_ = __shfl_sync(0xffffffffu, act, j8 + 16);
            float o_ = __shfl_sync(0xffffffffu, act, j8 + 24);

            c = fmaf(f_, c, i_ * g_);
            float hn = o_ * tanh_fast(c);

            h0 = __shfl_sync(0xffffffffu, hn, 0);
            h1 = __shfl_sync(0xffffffffu, hn, 1);
            h2 = __shfl_sync(0xffffffffu, hn, 2);
            h3 = __shfl_sync(0xffffffffu, hn, 3);
            h4 = __shfl_sync(0xffffffffu, hn, 4);
            h5 = __shfl_sync(0xffffffffu, hn, 5);
            h6 = __shfl_sync(0xffffffffu, hn, 6);
            h7 = __shfl_sync(0xffffffffu, hn, 7);

            if (lane < HID) hbuf[t * HID + lane] = hn;
            xp = xpn;
        }
    }
    __syncthreads();

    // ---- Phase 5a: fc_out, warp w handles t = w, w+16 — pure smem ----
    for (int t = warp; t < TT; t += NWARP) {
        float acc1 = sbo[lane];
        float acc2 = (lane < VV - 32) ? sbo[32 + lane] : 0.0f;
        #pragma unroll
        for (int j = 0; j < HID; ++j) {
            float hv = hbuf[t * HID + j];
            acc1 = fmaf(hv, sWout[lane * 9 + j], acc1);
            if (lane < VV - 32)
                acc2 = fmaf(hv, sWout[(32 + lane) * 9 + j], acc2);
        }
        logits[t * VV + lane] = acc1;
        if (lane < VV - 32) logits[t * VV + 32 + lane] = acc2;
    }
    __syncthreads();

    // ---- Phase 5b: parallel softmax over TIME + fused store ----
    {
        const int sg = lane >> 3;            // 0..3
        const int sl = lane & 7;             // t = sl, sl+8, sl+16, sl+24
        const int v  = warp * 4 + sg;        // 0..63; valid if < VV
        const int vc = (v < VV) ? v : 0;

        float x0 = logits[(sl     ) * VV + vc];
        float x1 = logits[(sl +  8) * VV + vc];
        float x2 = logits[(sl + 16) * VV + vc];
        float x3 = logits[(sl + 24) * VV + vc];

        float m = fmaxf(fmaxf(x0, x1), fmaxf(x2, x3));
        #pragma unroll
        for (int o = 4; o > 0; o >>= 1)
            m = fmaxf(m, __shfl_xor_sync(0xffffffffu, m, o, 8));

        float e0 = __expf(x0 - m);
        float e1 = __expf(x1 - m);
        float e2 = __expf(x2 - m);
        float e3 = __expf(x3 - m);
        float s = (e0 + e1) + (e2 + e3);
        #pragma unroll
        for (int o = 4; o > 0; o >>= 1)
            s += __shfl_xor_sync(0xffffffffu, s, o, 8);
        float r = 1.0f / s;

        if (v < VV) {
            float* ob = out + (size_t)b * TT * VV + v;
            ob[(sl     ) * VV] = e0 * r;
            ob[(sl +  8) * VV] = e1 * r;
            ob[(sl + 16) * VV] = e2 * r;
            ob[(sl + 24) * VV] = e3 * r;
        }
    }
}

// ---------------------------------------------------------------------------
extern "C" void kernel_launch(void* const* d_in, const int* in_sizes, int n_in,
                              void* d_out, int out_size)
{
    const float* features = (const float*)d_in[0];
    const float* captions = (const float*)d_in[1];
    const float* W_ih     = (const float*)d_in[2];
    const float* b_ih     = (const float*)d_in[3];
    const float* W_hh     = (const float*)d_in[4];
    const float* b_hh     = (const float*)d_in[5];
    const float* W_in     = (const float*)d_in[6];
    const float* b_in     = (const float*)d_in[7];
    const float* W_out    = (const float*)d_in[8];
    const float* b_out    = (const float*)d_in[9];
    float* out = (float*)d_out;

    lstm_fused_kernel<<<BB, NTHR>>>(features, captions, W_ih, b_ih, W_hh, b_hh,
                                    W_in, b_in, W_out, b_out, out);
    (void)in_sizes; (void)n_in; (void)out_size;
}